// round 14
// baseline (speedup 1.0000x reference)
#include <cuda_runtime.h>
#include <cuda_bf16.h>
#include <cstdint>

#define N_SAMPLES   8192
#define CODE_LEN    128
#define NUM_CLASSES 1000
#define NCLASS_PAD  1024
#define NB_MAIN     1024
#define NB_MID      128
#define M_TILES     64            // 8192 / 128
#define N_TILES     32            // 1024 / 32
#define NB_GEMM     (M_TILES * N_TILES)
#define SA_STRIDE   136           // 128 + 8 bf16 pad -> conflict-free frag LDS

// ---- device scratch (zero-init at load; self-cleaning across graph replays) ----
__device__ unsigned       d_used[NUM_CLASSES];          // k_main sets, k_gemm last block zeroes
__device__ __nv_bfloat16  d_pred[N_SAMPLES * CODE_LEN]; // predictions as bf16 0/1
__device__ __nv_bfloat16  d_cwb[NCLASS_PAD * CODE_LEN]; // masked codewords as bf16 0/1
__device__ float          d_spf[N_SAMPLES];             // per-sample bit count
__device__ float          d_scf[NCLASS_PAD];            // per-(masked)class bit count
__device__ unsigned       d_mn[N_SAMPLES];              // per-sample min; re-init by k_main
__device__ float          d_bce_part[NB_MAIN];
__device__ int            d_done;                       // reset by k_gemm last block

// ---------------------------------------------------------------------------
// K1: one warp per sample. pred->bf16 + sp popcount + used-mark + BCE.
__global__ void k_main(const float* __restrict__ out_p,
                       const float* __restrict__ cw,
                       const int*   __restrict__ tgt) {
    __shared__ float wsum[8];
    int gw   = (blockIdx.x * blockDim.x + threadIdx.x) >> 5;  // 0..8191
    int lane = threadIdx.x & 31;
    int wid  = threadIdx.x >> 5;

    if (threadIdx.x < 8)
        d_mn[blockIdx.x * 8 + threadIdx.x] = 0xffffffffu;

    int t  = tgt[gw];
    int tc = (t < 0) ? 0 : ((t >= NUM_CLASSES) ? NUM_CLASSES - 1 : t);

    float4 v = reinterpret_cast<const float4*>(out_p + (size_t)gw * CODE_LEN)[lane];
    unsigned b0 = v.x > 0.5f, b1 = v.y > 0.5f, b2 = v.z > 0.5f, b3 = v.w > 0.5f;
    unsigned pw0 = (b0 ? 0x3F80u : 0u) | (b1 ? 0x3F800000u : 0u);  // bf16 1.0 pair
    unsigned pw1 = (b2 ? 0x3F80u : 0u) | (b3 ? 0x3F800000u : 0u);
    reinterpret_cast<uint2*>(d_pred)[gw * 32 + lane] = make_uint2(pw0, pw1);

    unsigned sp = __reduce_add_sync(0xffffffffu, b0 + b1 + b2 + b3);
    if (lane == 0) { d_spf[gw] = (float)sp; d_used[tc] = 1u; }

    // BCE via fast log (validated earlier: rel_err 8e-8, tol 1e-3)
    float4 c4 = reinterpret_cast<const float4*>(cw + (size_t)tc * CODE_LEN)[lane];
    float a0 = (c4.x > 0.5f) ? v.x : (1.0f - v.x);
    float a1 = (c4.y > 0.5f) ? v.y : (1.0f - v.y);
    float a2 = (c4.z > 0.5f) ? v.z : (1.0f - v.z);
    float a3 = (c4.w > 0.5f) ? v.w : (1.0f - v.w);
    float bce = -(__logf(a0) + __logf(a1) + __logf(a2) + __logf(a3));

    #pragma unroll
    for (int off = 16; off > 0; off >>= 1)
        bce += __shfl_down_sync(0xffffffffu, bce, off);
    if (lane == 0) wsum[wid] = bce;
    __syncthreads();
    if (wid == 0) {
        float s = (lane < 8) ? wsum[lane] : 0.0f;
        #pragma unroll
        for (int off = 4; off > 0; off >>= 1)
            s += __shfl_down_sync(0xffffffffu, s, off);
        if (lane == 0) d_bce_part[blockIdx.x] = s;
    }
}

// ---------------------------------------------------------------------------
// K2 (tiny): one warp per padded class slot. Unused/pad slots take the codeword
// of a guaranteed-used class (target[0]) -> min over rows == min over used set.
__global__ void k_mid(const float* __restrict__ cw,
                      const int*   __restrict__ tgt) {
    int c    = (blockIdx.x * blockDim.x + threadIdx.x) >> 5;  // 0..1023
    int lane = threadIdx.x & 31;

    int t0 = tgt[0];
    int fb = (t0 < 0) ? 0 : ((t0 >= NUM_CLASSES) ? NUM_CLASSES - 1 : t0);
    int s  = (c < NUM_CLASSES && d_used[c]) ? c : fb;

    float4 v = reinterpret_cast<const float4*>(cw + (size_t)s * CODE_LEN)[lane];
    unsigned b0 = v.x > 0.5f, b1 = v.y > 0.5f, b2 = v.z > 0.5f, b3 = v.w > 0.5f;
    unsigned pw0 = (b0 ? 0x3F80u : 0u) | (b1 ? 0x3F800000u : 0u);
    unsigned pw1 = (b2 ? 0x3F80u : 0u) | (b3 ? 0x3F800000u : 0u);
    reinterpret_cast<uint2*>(d_cwb)[c * 32 + lane] = make_uint2(pw0, pw1);

    unsigned sc = __reduce_add_sync(0xffffffffu, b0 + b1 + b2 + b3);
    if (lane == 0) d_scf[c] = (float)sc;
}

// ---------------------------------------------------------------------------
// K3: tensor-core distance-min. Block tile M128 x N32 x K128 (static smem
// < 48KB, no attribute call). 8 warps x m16n32.
// dist[i][j] = sp_i + sc_j - 2 * <pred_i, cw_j>  (exact integers in fp32).
__global__ void __launch_bounds__(256) k_gemm(float* __restrict__ out) {
    __shared__ __nv_bfloat16 sA[128 * SA_STRIDE];   // 34816 B
    __shared__ __nv_bfloat16 sB[32 * SA_STRIDE];    //  8704 B
    __shared__ float    sSP[128];
    __shared__ float    sSC[32];
    __shared__ float    fred[8];
    __shared__ unsigned ured[8];
    __shared__ int      s_last;

    int tid = threadIdx.x, lane = tid & 31, w = tid >> 5;
    int m0 = blockIdx.x * 128;
    int n0 = blockIdx.y * 32;

    // load tiles (row = i>>4, 16B seg = i&15; stride 136 bf16 = 272 B, 16B-aligned)
    const uint4* gA = (const uint4*)(d_pred + (size_t)m0 * CODE_LEN);
    #pragma unroll
    for (int i = tid; i < 2048; i += 256) {
        int r = i >> 4, s = i & 15;
        ((uint4*)(sA + r * SA_STRIDE))[s] = gA[i];
    }
    const uint4* gB = (const uint4*)(d_cwb + (size_t)n0 * CODE_LEN);
    {
        int i = tid, r = i >> 4, s = i & 15;    // exactly 512 uint4 for 256 thr x2
        ((uint4*)(sB + r * SA_STRIDE))[s] = gB[i];
        i += 256; r = i >> 4; s = i & 15;
        ((uint4*)(sB + r * SA_STRIDE))[s] = gB[i];
    }
    if (tid < 128) sSP[tid] = d_spf[m0 + tid];
    if (tid < 32)  sSC[tid] = d_scf[n0 + tid];
    __syncthreads();

    int g = lane >> 2, t = lane & 3;
    const __nv_bfloat16* arow0 = sA + (w * 16 + g) * SA_STRIDE;
    const __nv_bfloat16* arow1 = arow0 + 8 * SA_STRIDE;

    float acc[4][4];
    #pragma unroll
    for (int nn = 0; nn < 4; nn++)
        { acc[nn][0] = acc[nn][1] = acc[nn][2] = acc[nn][3] = 0.0f; }

    #pragma unroll
    for (int kk = 0; kk < 8; kk++) {
        int kb = kk * 16 + 2 * t;
        unsigned a0 = *(const unsigned*)(arow0 + kb);
        unsigned a1 = *(const unsigned*)(arow1 + kb);
        unsigned a2 = *(const unsigned*)(arow0 + kb + 8);
        unsigned a3 = *(const unsigned*)(arow1 + kb + 8);
        #pragma unroll
        for (int nn = 0; nn < 4; nn++) {
            const __nv_bfloat16* brow = sB + (nn * 8 + g) * SA_STRIDE;
            unsigned b0 = *(const unsigned*)(brow + kb);
            unsigned b1 = *(const unsigned*)(brow + kb + 8);
            asm volatile(
                "mma.sync.aligned.m16n8k16.row.col.f32.bf16.bf16.f32 "
                "{%0,%1,%2,%3}, {%4,%5,%6,%7}, {%8,%9}, {%0,%1,%2,%3};"
                : "+f"(acc[nn][0]), "+f"(acc[nn][1]),
                  "+f"(acc[nn][2]), "+f"(acc[nn][3])
                : "r"(a0), "r"(a1), "r"(a2), "r"(a3), "r"(b0), "r"(b1));
        }
    }

    // epilogue: dist = sp + sc - 2*dot; row-min over this block's 32 classes
    float sp0 = sSP[w * 16 + g], sp1 = sSP[w * 16 + g + 8];
    float r0 = 1e30f, r1 = 1e30f;
    #pragma unroll
    for (int nn = 0; nn < 4; nn++) {
        float sc0 = sSC[nn * 8 + 2 * t];
        float sc1 = sSC[nn * 8 + 2 * t + 1];
        r0 = fminf(r0, fminf(sp0 + sc0 - 2.0f * acc[nn][0],
                             sp0 + sc1 - 2.0f * acc[nn][1]));
        r1 = fminf(r1, fminf(sp1 + sc0 - 2.0f * acc[nn][2],
                             sp1 + sc1 - 2.0f * acc[nn][3]));
    }
    r0 = fminf(r0, __shfl_xor_sync(0xffffffffu, r0, 1));
    r0 = fminf(r0, __shfl_xor_sync(0xffffffffu, r0, 2));
    r1 = fminf(r1, __shfl_xor_sync(0xffffffffu, r1, 1));
    r1 = fminf(r1, __shfl_xor_sync(0xffffffffu, r1, 2));
    if (t == 0) {
        atomicMin(&d_mn[m0 + w * 16 + g],     __float2uint_rn(r0));
        atomicMin(&d_mn[m0 + w * 16 + g + 8], __float2uint_rn(r1));
    }

    __threadfence();
    __syncthreads();
    if (tid == 0) {
        int old = atomicAdd(&d_done, 1);
        s_last = (old == NB_GEMM - 1);
    }
    __syncthreads();

    // --- last block: final reduction + output + state reset ---
    if (s_last) {
        float fb = 0.0f;
        for (int i = tid; i < NB_MAIN; i += 256) fb += d_bce_part[i];
        unsigned sg = 0u;
        for (int i = tid; i < N_SAMPLES; i += 256) sg += d_mn[i];
        #pragma unroll
        for (int off = 16; off > 0; off >>= 1) {
            fb += __shfl_down_sync(0xffffffffu, fb, off);
            sg += __shfl_down_sync(0xffffffffu, sg, off);
        }
        if (lane == 0) { fred[w] = fb; ured[w] = sg; }
        __syncthreads();
        if (tid == 0) {
            float ftot = 0.0f; unsigned stot = 0;
            #pragma unroll
            for (int q = 0; q < 8; q++) { ftot += fred[q]; stot += ured[q]; }
            out[0] = (ftot + (float)CODE_LEN * (float)stot)
                   / (float)(N_SAMPLES * CODE_LEN);
            d_done = 0;
        }
        for (int c = tid; c < NUM_CLASSES; c += 256)
            d_used[c] = 0u;     // reset (k_mid consumed it earlier this replay)
    }
}

// ---------------------------------------------------------------------------
extern "C" void kernel_launch(void* const* d_in, const int* in_sizes, int n_in,
                              void* d_out, int out_size) {
    const float* out_p = (const float*)d_in[0];   // [8192,128] float32
    const float* cw_p  = (const float*)d_in[1];   // [1000,128] float32
    const int*   tgt_p = (const int*)d_in[2];     // [8192] int32

    k_main<<<NB_MAIN, 256>>>(out_p, cw_p, tgt_p);
    k_mid<<<NB_MID, 256>>>(cw_p, tgt_p);
    k_gemm<<<dim3(M_TILES, N_TILES), 256>>>((float*)d_out);
}

// round 16
// speedup vs baseline: 1.8130x; 1.8130x over previous
#include <cuda_runtime.h>
#include <cstdint>

#define N_SAMPLES   8192
#define CODE_LEN    128
#define NUM_CLASSES 1000
#define NB_MAIN     256      // 256 x 256thr = 2048 warps, 4 samples/warp
#define QUARTER     250      // classes per k_min quarter
#define QPAD        256      // padded
#define NB_MIN      1024     // (8192/32 sample-groups) x 4 quarters

// ---- device scratch (zero-init at load; self-cleaning across graph replays) ----
__device__ unsigned d_used[NUM_CLASSES];   // set in k_main, zeroed by k_min last block
__device__ uint4    d_cwbits[NUM_CLASSES]; // ballot-packed codewords
__device__ uint4    d_predbits[N_SAMPLES]; // ballot-packed predictions
__device__ unsigned d_mn[N_SAMPLES];       // per-sample min; re-init by k_main
__device__ float    d_bce_part[NB_MAIN];
__device__ int      d_done;                // reset by k_min last block

// ---------------------------------------------------------------------------
// K1: 4 samples per warp (MLP>=4 on the row loads). Ballot bit-packing for
//     preds AND codewords (same bit permutation -> Hamming preserved),
//     used-mark, fast-log BCE, d_mn re-init.
__global__ void k_main(const float* __restrict__ out_p,
                       const float* __restrict__ cw,
                       const int*   __restrict__ tgt) {
    __shared__ float wsum[8];
    int tid  = threadIdx.x;
    int lane = tid & 31, wid = tid >> 5;
    int gw   = blockIdx.x * 8 + wid;           // 0..2047

    if (tid < 32) d_mn[blockIdx.x * 32 + tid] = 0xffffffffu;

    // pack one codeword (warp-uniform branch; first 1000 warps)
    if (gw < NUM_CLASSES) {
        float4 c = reinterpret_cast<const float4*>(cw + (size_t)gw * CODE_LEN)[lane];
        unsigned b0 = __ballot_sync(0xffffffffu, c.x > 0.5f);
        unsigned b1 = __ballot_sync(0xffffffffu, c.y > 0.5f);
        unsigned b2 = __ballot_sync(0xffffffffu, c.z > 0.5f);
        unsigned b3 = __ballot_sync(0xffffffffu, c.w > 0.5f);
        if (lane == 0) d_cwbits[gw] = make_uint4(b0, b1, b2, b3);
    }

    int s0 = gw * 4;                           // 4 samples for this warp
    float4 v[4];
    #pragma unroll
    for (int i = 0; i < 4; i++)                // batched: 4 loads in flight
        v[i] = reinterpret_cast<const float4*>(out_p + (size_t)(s0 + i) * CODE_LEN)[lane];
    int tc[4];
    #pragma unroll
    for (int i = 0; i < 4; i++) {
        int t = tgt[s0 + i];
        tc[i] = (t < 0) ? 0 : ((t >= NUM_CLASSES) ? NUM_CLASSES - 1 : t);
    }

    float bce = 0.0f;
    #pragma unroll
    for (int i = 0; i < 4; i++) {
        unsigned b0 = __ballot_sync(0xffffffffu, v[i].x > 0.5f);
        unsigned b1 = __ballot_sync(0xffffffffu, v[i].y > 0.5f);
        unsigned b2 = __ballot_sync(0xffffffffu, v[i].z > 0.5f);
        unsigned b3 = __ballot_sync(0xffffffffu, v[i].w > 0.5f);
        if (lane == 0) {
            d_predbits[s0 + i] = make_uint4(b0, b1, b2, b3);
            d_used[tc[i]] = 1u;
        }
        float4 c4 = reinterpret_cast<const float4*>(cw + (size_t)tc[i] * CODE_LEN)[lane];
        float a0 = (c4.x > 0.5f) ? v[i].x : (1.0f - v[i].x);
        float a1 = (c4.y > 0.5f) ? v[i].y : (1.0f - v[i].y);
        float a2 = (c4.z > 0.5f) ? v[i].z : (1.0f - v[i].z);
        float a3 = (c4.w > 0.5f) ? v[i].w : (1.0f - v[i].w);
        bce -= __logf(a0) + __logf(a1) + __logf(a2) + __logf(a3);
    }

    #pragma unroll
    for (int off = 16; off > 0; off >>= 1)
        bce += __shfl_down_sync(0xffffffffu, bce, off);
    if (lane == 0) wsum[wid] = bce;
    __syncthreads();
    if (wid == 0) {
        float s = (lane < 8) ? wsum[lane] : 0.0f;
        #pragma unroll
        for (int off = 4; off > 0; off >>= 1)
            s += __shfl_down_sync(0xffffffffu, s, off);
        if (lane == 0) d_bce_part[blockIdx.x] = s;
    }
}

__device__ __forceinline__ unsigned ham4(uint4 a, uint4 b) {
    return __popc(a.x ^ b.x) + __popc(a.y ^ b.y)
         + __popc(a.z ^ b.z) + __popc(a.w ^ b.w);
}

// ---------------------------------------------------------------------------
// K2: 1024 blocks x 128 thr. Block = 32 samples x one class-quarter (250 pad
//     256; unused/pad slots -> codeword of a known-used class: min-invariant).
//     Thread = 4 samples x 1/16 slice: one LDS feeds 4 independent min chains
//     (ILP=4) at ~7 blocks/SM. Cross-quarter combine via atomicMin(d_mn).
__global__ void __launch_bounds__(128) k_min(float* __restrict__ out,
                                             const int* __restrict__ tgt) {
    __shared__ uint4    cwl[QPAD];
    __shared__ unsigned ured[4];
    __shared__ float    fred[4];
    __shared__ int      s_last;

    int tid  = threadIdx.x;
    int lane = tid & 31, w = tid >> 5;
    int q     = blockIdx.x & 3;                // class quarter
    int sbase = (blockIdx.x >> 2) * 32;        // sample base

    int t0 = tgt[0];
    int fb = (t0 < 0) ? 0 : ((t0 >= NUM_CLASSES) ? NUM_CLASSES - 1 : t0);

    #pragma unroll
    for (int k = tid; k < QPAD; k += 128) {
        int g = q * QUARTER + k;               // < 1000 when k < QUARTER
        bool live = (k < QUARTER) && (d_used[g] != 0u);
        cwl[k] = live ? d_cwbits[g] : d_cwbits[fb];
    }
    __syncthreads();

    int sub = tid & 15;                        // class-slice (16 iters)
    int grp = tid >> 4;                        // 8 groups x 4 samples
    int s   = sbase + grp * 4;
    uint4 x0 = d_predbits[s + 0];
    uint4 x1 = d_predbits[s + 1];
    uint4 x2 = d_predbits[s + 2];
    uint4 x3 = d_predbits[s + 3];

    unsigned m0 = 0xffffffffu, m1 = 0xffffffffu, m2 = 0xffffffffu, m3 = 0xffffffffu;
    #pragma unroll 4
    for (int k = sub; k < QPAD; k += 16) {
        uint4 c = cwl[k];
        m0 = min(m0, ham4(x0, c));
        m1 = min(m1, ham4(x1, c));
        m2 = min(m2, ham4(x2, c));
        m3 = min(m3, ham4(x3, c));
    }
    // combine 16 slices (offsets stay within each 16-lane half)
    #pragma unroll
    for (int off = 1; off < 16; off <<= 1) {
        m0 = min(m0, __shfl_xor_sync(0xffffffffu, m0, off));
        m1 = min(m1, __shfl_xor_sync(0xffffffffu, m1, off));
        m2 = min(m2, __shfl_xor_sync(0xffffffffu, m2, off));
        m3 = min(m3, __shfl_xor_sync(0xffffffffu, m3, off));
    }
    if (sub == 0) {
        atomicMin(&d_mn[s + 0], m0);
        atomicMin(&d_mn[s + 1], m1);
        atomicMin(&d_mn[s + 2], m2);
        atomicMin(&d_mn[s + 3], m3);
    }

    __threadfence();
    __syncthreads();
    if (tid == 0) {
        int old = atomicAdd(&d_done, 1);
        s_last = (old == NB_MIN - 1);
    }
    __syncthreads();

    // --- last block: final reduction + output + state reset ---
    if (s_last) {
        float fbce = 0.0f;
        for (int i = tid; i < NB_MAIN; i += 128) fbce += d_bce_part[i];
        unsigned sg = 0u;
        for (int i = tid; i < N_SAMPLES; i += 128) sg += d_mn[i];
        #pragma unroll
        for (int off = 16; off > 0; off >>= 1) {
            fbce += __shfl_down_sync(0xffffffffu, fbce, off);
            sg   += __shfl_down_sync(0xffffffffu, sg, off);
        }
        if (lane == 0) { fred[w] = fbce; ured[w] = sg; }
        __syncthreads();
        if (tid == 0) {
            float ftot = 0.0f; unsigned stot = 0;
            #pragma unroll
            for (int k = 0; k < 4; k++) { ftot += fred[k]; stot += ured[k]; }
            out[0] = (ftot + (float)CODE_LEN * (float)stot)
                   / (float)(N_SAMPLES * CODE_LEN);
            d_done = 0;                        // reset for next replay
        }
        for (int c = tid; c < NUM_CLASSES; c += 128)
            d_used[c] = 0u;                    // reset (every block read d_used
                                               // before its d_done increment)
        // d_mn re-initialized by k_main next replay
    }
}

// ---------------------------------------------------------------------------
extern "C" void kernel_launch(void* const* d_in, const int* in_sizes, int n_in,
                              void* d_out, int out_size) {
    const float* out_p = (const float*)d_in[0];   // [8192,128] float32
    const float* cw_p  = (const float*)d_in[1];   // [1000,128] float32
    const int*   tgt_p = (const int*)d_in[2];     // [8192] int32

    k_main<<<NB_MAIN, 256>>>(out_p, cw_p, tgt_p);
    k_min<<<NB_MIN, 128>>>((float*)d_out, tgt_p);
}